// round 2
// baseline (speedup 1.0000x reference)
#include <cuda_runtime.h>

#define L  4096
#define V  50257
#define H1 30
#define H2 50
#define G1 120   // 4*H1
#define G2 200   // 4*H2

// scratch (device globals: no allocation allowed)
__device__ float g_gx1[L * G1];
__device__ float g_h1 [L * H1];
__device__ float g_mid[L * H2];
__device__ float g_gx2[L * G2];
__device__ float g_h2 [L * H2];

typedef unsigned long long u64;

__device__ __forceinline__ u64 pk2(float lo, float hi) {
    u64 r; asm("mov.b64 %0, {%1, %2};" : "=l"(r) : "f"(lo), "f"(hi)); return r;
}
__device__ __forceinline__ u64 ffma2(u64 a, u64 b, u64 c) {
    u64 d; asm("fma.rn.f32x2 %0, %1, %2, %3;" : "=l"(d) : "l"(a), "l"(b), "l"(c)); return d;
}
__device__ __forceinline__ u64 fadd2(u64 a, u64 b) {
    u64 d; asm("add.rn.f32x2 %0, %1, %2;" : "=l"(d) : "l"(a), "l"(b)); return d;
}
__device__ __forceinline__ float hsum2(u64 a) {
    float x, y; asm("mov.b64 {%0, %1}, %2;" : "=f"(x), "=f"(y) : "l"(a)); return x + y;
}

// fast-but-accurate transcendentals (~2^-21 rel err; tanh.approx is too sloppy
// at ~5e-4 abs for a 4096-step recurrence feeding a 1e-3 tolerance)
__device__ __forceinline__ float fexp(float x) {
    float y; asm("ex2.approx.f32 %0, %1;" : "=f"(y) : "f"(x * 1.4426950408889634f)); return y;
}
__device__ __forceinline__ float frcp(float x) {
    float y; asm("rcp.approx.f32 %0, %1;" : "=f"(y) : "f"(x)); return y;
}
__device__ __forceinline__ float sigm(float x)   { return frcp(1.0f + fexp(-x)); }
__device__ __forceinline__ float tanh_f(float x) { return 1.0f - 2.0f * frcp(fexp(2.0f * x) + 1.0f); }

// ---------------------------------------------------------------------------
// K1: gx1[t][j] = emb[x[t]] . w_ih1[j] + b_ih1[j] + b_hh1[j]
// ---------------------------------------------------------------------------
__global__ void k_gx1(const int* __restrict__ x, const float* __restrict__ emb,
                      const float* __restrict__ w_ih1, const float* __restrict__ b_ih1,
                      const float* __restrict__ b_hh1) {
    int idx = blockIdx.x * blockDim.x + threadIdx.x;
    if (idx >= L * G1) return;
    int t = idx / G1, j = idx % G1;
    const float* er = emb + (long)x[t] * H1;
    const float* wr = w_ih1 + j * H1;
    float s = b_ih1[j] + b_hh1[j];
#pragma unroll
    for (int k = 0; k < H1; k++) s += er[k] * wr[k];
    g_gx1[idx] = s;
}

// ---------------------------------------------------------------------------
// K2: LSTM layer 1 scan (single CTA, 128 threads; 120 gate threads)
// ---------------------------------------------------------------------------
__global__ void k_lstm1(const float* __restrict__ w_hh1) {
    __shared__ __align__(16) float h_sh[32];
    __shared__ float act_sh[G1];
    int j = threadIdx.x;

    u64 wr[H1 / 2];
    if (j < G1) {
        const float* w = w_hh1 + j * H1;
#pragma unroll
        for (int m = 0; m < H1 / 2; m++) wr[m] = pk2(w[2 * m], w[2 * m + 1]);
    }
    if (j < 32) h_sh[j] = 0.0f;
    float c = 0.0f;
    __syncthreads();

    const int CH = 8;
    float gxr[CH];
    for (int t0 = 0; t0 < L; t0 += CH) {
        if (j < G1) {
#pragma unroll
            for (int k = 0; k < CH; k++) gxr[k] = g_gx1[(t0 + k) * G1 + j];
        }
#pragma unroll
        for (int k = 0; k < CH; k++) {
            if (j < G1) {
                const u64* hp = (const u64*)h_sh;
                u64 a0 = pk2(gxr[k], 0.0f), a1 = pk2(0.0f, 0.0f);
#pragma unroll
                for (int m = 0; m < H1 / 2; m += 2) a0 = ffma2(wr[m], hp[m], a0);
#pragma unroll
                for (int m = 1; m < H1 / 2; m += 2) a1 = ffma2(wr[m], hp[m], a1);
                float s = hsum2(fadd2(a0, a1));
                act_sh[j] = (j >= 2 * H1 && j < 3 * H1) ? tanh_f(s) : sigm(s);
            }
            __syncthreads();
            if (j < H1) {
                float ai = act_sh[j], af = act_sh[j + H1];
                float ag = act_sh[j + 2 * H1], ao = act_sh[j + 3 * H1];
                c = af * c + ai * ag;
                float h = ao * tanh_f(c);
                h_sh[j] = h;
                g_h1[(t0 + k) * H1 + j] = h;
            }
            __syncthreads();
        }
    }
}

// ---------------------------------------------------------------------------
// K3a: mid[t][m] = h1[t] . w1[m] + bl1[m]
// ---------------------------------------------------------------------------
__global__ void k_mid(const float* __restrict__ w1, const float* __restrict__ bl1) {
    int idx = blockIdx.x * blockDim.x + threadIdx.x;
    if (idx >= L * H2) return;
    int t = idx / H2, m = idx % H2;
    const float* hr = g_h1 + t * H1;
    const float* w  = w1 + m * H1;
    float s = bl1[m];
#pragma unroll
    for (int k = 0; k < H1; k++) s += hr[k] * w[k];
    g_mid[idx] = s;
}

// ---------------------------------------------------------------------------
// K3b: gx2[t][j] = mid[t] . w_ih2[j] + b_ih2[j] + b_hh2[j]
// ---------------------------------------------------------------------------
__global__ void k_gx2(const float* __restrict__ w_ih2, const float* __restrict__ b_ih2,
                      const float* __restrict__ b_hh2) {
    int idx = blockIdx.x * blockDim.x + threadIdx.x;
    if (idx >= L * G2) return;
    int t = idx / G2, j = idx % G2;
    const float* mr = g_mid + t * H2;
    const float* w  = w_ih2 + j * H2;
    float s = b_ih2[j] + b_hh2[j];
#pragma unroll
    for (int k = 0; k < H2; k++) s += mr[k] * w[k];
    g_gx2[idx] = s;
}

// ---------------------------------------------------------------------------
// K4: LSTM layer 2 scan (single CTA, 256 threads; 200 gate threads)
// ---------------------------------------------------------------------------
__global__ void k_lstm2(const float* __restrict__ w_hh2) {
    __shared__ __align__(16) float h_sh[56];
    __shared__ float act_sh[G2];
    int j = threadIdx.x;

    u64 wr[H2 / 2];
    if (j < G2) {
        const float* w = w_hh2 + j * H2;
#pragma unroll
        for (int m = 0; m < H2 / 2; m++) wr[m] = pk2(w[2 * m], w[2 * m + 1]);
    }
    if (j < 56) h_sh[j] = 0.0f;
    float c = 0.0f;
    __syncthreads();

    const int CH = 8;
    float gxr[CH];
    for (int t0 = 0; t0 < L; t0 += CH) {
        if (j < G2) {
#pragma unroll
            for (int k = 0; k < CH; k++) gxr[k] = g_gx2[(t0 + k) * G2 + j];
        }
#pragma unroll
        for (int k = 0; k < CH; k++) {
            if (j < G2) {
                const u64* hp = (const u64*)h_sh;
                u64 a0 = pk2(gxr[k], 0.0f), a1 = pk2(0.0f, 0.0f);
#pragma unroll
                for (int m = 0; m < H2 / 2; m += 2) a0 = ffma2(wr[m], hp[m], a0);
#pragma unroll
                for (int m = 1; m < H2 / 2; m += 2) a1 = ffma2(wr[m], hp[m], a1);
                float s = hsum2(fadd2(a0, a1));
                act_sh[j] = (j >= 2 * H2 && j < 3 * H2) ? tanh_f(s) : sigm(s);
            }
            __syncthreads();
            if (j < H2) {
                float ai = act_sh[j], af = act_sh[j + H2];
                float ag = act_sh[j + 2 * H2], ao = act_sh[j + 3 * H2];
                c = af * c + ai * ag;
                float h = ao * tanh_f(c);
                h_sh[j] = h;
                g_h2[(t0 + k) * H2 + j] = h;
            }
            __syncthreads();
        }
    }
}

// ---------------------------------------------------------------------------
// K5: out[t][v] = h2[t] . w2[v] + bl2[v]   (f32x2 packed FMA, 2 MACs/inst)
// grid: (ceil(V/128), 4); each y-slice handles 1024 timesteps
// ---------------------------------------------------------------------------
__global__ void k_out(const float* __restrict__ w2, const float* __restrict__ bl2,
                      float* __restrict__ out) {
    __shared__ __align__(16) float h_sh[32 * H2];
    int v = blockIdx.x * blockDim.x + threadIdx.x;
    bool active = (v < V);

    u64 wr[H2 / 2];
    float bias = 0.0f;
    if (active) {
        const float* w = w2 + (long)v * H2;
#pragma unroll
        for (int m = 0; m < H2 / 2; m++) wr[m] = pk2(w[2 * m], w[2 * m + 1]);
        bias = bl2[v];
    }

    int tbeg = blockIdx.y * (L / 4);
    int tend = tbeg + (L / 4);
    for (int t0 = tbeg; t0 < tend; t0 += 32) {
        __syncthreads();
        for (int i = threadIdx.x; i < 32 * H2; i += blockDim.x)
            h_sh[i] = g_h2[t0 * H2 + i];
        __syncthreads();
#pragma unroll 2
        for (int tt = 0; tt < 32; tt++) {
            const u64* hp = (const u64*)(h_sh + tt * H2);
            u64 a0 = pk2(0.0f, 0.0f), a1 = pk2(0.0f, 0.0f);
#pragma unroll
            for (int m = 0; m < H2 / 2; m += 2) a0 = ffma2(wr[m], hp[m], a0);
#pragma unroll
            for (int m = 1; m < H2 / 2; m += 2) a1 = ffma2(wr[m], hp[m], a1);
            if (active)
                out[(long)(t0 + tt) * V + v] = hsum2(fadd2(a0, a1)) + bias;
        }
    }
}

// ---------------------------------------------------------------------------
extern "C" void kernel_launch(void* const* d_in, const int* in_sizes, int n_in,
                              void* d_out, int out_size) {
    const int*   x     = (const int*)  d_in[0];
    const float* emb   = (const float*)d_in[1];
    const float* w_ih1 = (const float*)d_in[2];
    const float* w_hh1 = (const float*)d_in[3];
    const float* b_ih1 = (const float*)d_in[4];
    const float* b_hh1 = (const float*)d_in[5];
    const float* w1    = (const float*)d_in[6];
    const float* bl1   = (const float*)d_in[7];
    const float* w_ih2 = (const float*)d_in[8];
    const float* w_hh2 = (const float*)d_in[9];
    const float* b_ih2 = (const float*)d_in[10];
    const float* b_hh2 = (const float*)d_in[11];
    const float* w2    = (const float*)d_in[12];
    const float* bl2   = (const float*)d_in[13];
    float* out = (float*)d_out;

    k_gx1 <<<(L * G1 + 255) / 256, 256>>>(x, emb, w_ih1, b_ih1, b_hh1);
    k_lstm1<<<1, 128>>>(w_hh1);
    k_mid <<<(L * H2 + 255) / 256, 256>>>(w1, bl1);
    k_gx2 <<<(L * G2 + 255) / 256, 256>>>(w_ih2, b_ih2, b_hh2);
    k_lstm2<<<1, 256>>>(w_hh2);
    dim3 g5((V + 127) / 128, 4);
    k_out <<<g5, 128>>>(w2, bl2, out);
}